// round 11
// baseline (speedup 1.0000x reference)
#include <cuda_runtime.h>
#include <cuda_fp16.h>
#include <cstdint>

// GridSample1d: N=64, C=64, L_in=4096, L_out=8192, fp32 in/out,
// align_corners=True, padding=border.
//
// R11: CG=2 paired-tap fp16 layout. Position i stores 8B =
// {h2(c0[i],c1[i]), h2(c0[i+1],c1[i+1])} -> ONE LDS.64 per (sample, 2ch)
// fetches both bilinear taps: gather crossbar bytes halve vs R9 (the
// binding term), no i1 computation. R9's proven shape otherwise:
// 256 thr, 444 persistent blocks (3/SM), 2x32KB double buffer, VEC=4.

#define N_B     64
#define C_TOT   64
#define L_IN    4096
#define L_OUT   8192
#define CG      2
#define NGRP    (C_TOT / CG)        // 32
#define TILES   (N_B * NGRP)        // 2048
#define THREADS 256
#define BLOCKS  444                 // 3 * 148 SMs (smem-limited)
#define BUF_B   (L_IN * 8)          // 32 KB per buffer (uint2 per position)
#define VEC     4
#define GITERS  (L_OUT / (THREADS * VEC))   // 8

__device__ __forceinline__ uint32_t swz(uint32_t o) {
    return o ^ ((o >> 3) & 0x70);
}
__device__ __forceinline__ uint32_t packh2(float a, float b) {
    __half2 h = __floats2half2_rn(a, b);
    return *reinterpret_cast<uint32_t*>(&h);
}

// staging chunk: 4 consecutive positions x 2 channels, needs v[i0..i0+4]
__device__ __forceinline__ void ldg_chunk(const float* ibase, int i0,
                                          float4 a[CG], float a4[CG]) {
    const int i4 = min(i0 + 4, L_IN - 1);
    #pragma unroll
    for (int c = 0; c < CG; ++c) {
        a[c]  = __ldcs(reinterpret_cast<const float4*>(ibase + (size_t)c * L_IN + i0));
        a4[c] = __ldcs(ibase + (size_t)c * L_IN + i4);
    }
}
__device__ __forceinline__ void sts_chunk(char* buf, int i0,
                                          const float4 a[CG], const float a4[CG]) {
    #pragma unroll
    for (int k = 0; k < 4; ++k) {
        float c0k  = ((const float*)&a[0])[k];
        float c1k  = ((const float*)&a[1])[k];
        float c0k1 = (k < 3) ? ((const float*)&a[0])[k + 1] : a4[0];
        float c1k1 = (k < 3) ? ((const float*)&a[1])[k + 1] : a4[1];
        uint2 v;
        v.x = packh2(c0k,  c1k);    // tap i+k,   channels 0,1
        v.y = packh2(c0k1, c1k1);   // tap i+k+1, channels 0,1
        *reinterpret_cast<uint2*>(buf + swz((uint32_t)(i0 + k) * 8u)) = v;
    }
}

__device__ __forceinline__ void gather_iter(int it, int tid, const char* cur,
                                            const float* grow, float* obase,
                                            float scale) {
    const int l0 = it * (THREADS * VEC) + tid * VEC;
    const float4 g = __ldg(reinterpret_cast<const float4*>(grow + l0));
    const float xs[VEC] = {g.x, g.y, g.z, g.w};
    float r[CG][VEC];

    #pragma unroll
    for (int j = 0; j < VEC; ++j) {
        float x = (xs[j] + 1.0f) * scale;               // align_corners
        x = fminf(fmaxf(x, 0.0f), (float)(L_IN - 1));   // border clamp
        float xf = floorf(x);
        int   i0 = (int)xf;
        float w1 = x - xf;
        float w0 = 1.0f - w1;

        // ONE LDS.64: both taps x 2 channels
        const uint2 p = *reinterpret_cast<const uint2*>(cur + swz((uint32_t)i0 * 8u));
        float2 v0 = __half22float2(*reinterpret_cast<const __half2*>(&p.x));
        float2 v1 = __half22float2(*reinterpret_cast<const __half2*>(&p.y));

        r[0][j] = w0 * v0.x + w1 * v1.x;
        r[1][j] = w0 * v0.y + w1 * v1.y;
    }

    #pragma unroll
    for (int c = 0; c < CG; ++c) {
        float4 o = make_float4(r[c][0], r[c][1], r[c][2], r[c][3]);
        __stcs(reinterpret_cast<float4*>(obase + (size_t)c * L_OUT + l0), o);
    }
}

__global__ __launch_bounds__(THREADS)
void gs1d_kernel(const float* __restrict__ inp,
                 const float* __restrict__ grid,
                 float* __restrict__ out)
{
    extern __shared__ char s_raw[];   // 2 x 32 KB paired-tap fp16, swizzled

    const int tid = threadIdx.x;
    const int b   = blockIdx.x;
    const float scale = 0.5f * (float)(L_IN - 1);
    const int iq0 = tid * 4;          // chunks at iq0 + q*1024, q=0..3

    // ---- prologue: stage first tile into buf 0 ----
    {
        const int t = b;
        const int n = t >> 5, c0 = (t & 31) * CG;
        const float* ibase = inp + ((size_t)n * C_TOT + c0) * L_IN;
        float4 a[CG]; float a4[CG];
        #pragma unroll
        for (int q = 0; q < 4; ++q) {
            ldg_chunk(ibase, iq0 + q * 1024, a, a4);
            sts_chunk(s_raw, iq0 + q * 1024, a, a4);
        }
    }
    __syncthreads();

    int k = 0;
    for (int t = b; t < TILES; t += BLOCKS, ++k) {
        char* cur = s_raw + (k & 1) * BUF_B;
        char* nxt = s_raw + ((k + 1) & 1) * BUF_B;

        const int n = t >> 5, c0 = (t & 31) * CG;
        const float* grow  = grid + (size_t)n * L_OUT;
        float*       obase = out  + ((size_t)n * C_TOT + c0) * L_OUT;

        const int  tn       = t + BLOCKS;
        const bool has_next = (tn < TILES);
        const float* nbase  = inp;
        if (has_next) {
            const int nn = tn >> 5, nc0 = (tn & 31) * CG;
            nbase = inp + ((size_t)nn * C_TOT + nc0) * L_IN;
        }

        float4 a[CG]; float a4[CG];
        if (has_next) ldg_chunk(nbase, iq0, a, a4);
        gather_iter(0, tid, cur, grow, obase, scale);
        if (has_next) { sts_chunk(nxt, iq0, a, a4); ldg_chunk(nbase, iq0 + 1024, a, a4); }
        gather_iter(1, tid, cur, grow, obase, scale);
        if (has_next) { sts_chunk(nxt, iq0 + 1024, a, a4); ldg_chunk(nbase, iq0 + 2048, a, a4); }
        gather_iter(2, tid, cur, grow, obase, scale);
        if (has_next) { sts_chunk(nxt, iq0 + 2048, a, a4); ldg_chunk(nbase, iq0 + 3072, a, a4); }
        gather_iter(3, tid, cur, grow, obase, scale);
        if (has_next) sts_chunk(nxt, iq0 + 3072, a, a4);
        gather_iter(4, tid, cur, grow, obase, scale);
        gather_iter(5, tid, cur, grow, obase, scale);
        gather_iter(6, tid, cur, grow, obase, scale);
        gather_iter(7, tid, cur, grow, obase, scale);
        __syncthreads();   // nxt fully staged; cur free for reuse
    }
}

extern "C" void kernel_launch(void* const* d_in, const int* in_sizes, int n_in,
                              void* d_out, int out_size)
{
    const float* inp  = (const float*)d_in[0];  // [64, 64, 4096]
    const float* grid = (const float*)d_in[1];  // [64, 8192]
    float*       out  = (float*)d_out;          // [64, 64, 8192]

    const int smem_bytes = 2 * BUF_B;           // 64 KB
    cudaFuncSetAttribute(gs1d_kernel,
                         cudaFuncAttributeMaxDynamicSharedMemorySize,
                         smem_bytes);

    gs1d_kernel<<<BLOCKS, THREADS, smem_bytes>>>(inp, grid, out);
}